// round 16
// baseline (speedup 1.0000x reference)
#include <cuda_runtime.h>
#include <cstdint>

// ---------------------------------------------------------------------------
// MHA forward: out = (softmax_causal(QK^T/sqrt(D)) V) Wo^T,  also emit attn.
// B=4, L=2048, E=1024, H=16, D=64.
// d_out layout: [out: B*L*E floats][attn: B*H*L*L floats]
// 3xBF16 m16n8k16 everywhere; operands pre-packed bf16 hi/lo in gmem;
// ldmatrix fragment loads.
// R16: GEMMs go 4-STAGE cp.async (BK=32, 160KB smem, 1 CTA/SM, wait_group 2,
// empty-commit tail). R15 was latency-exposed at prefetch distance 1
// (tensor 56%, issue 14%). Attention unchanged from R15 (best).
// ---------------------------------------------------------------------------

constexpr int B_ = 4, L_ = 2048, E_ = 1024, H_ = 16, D_ = 64;
constexpr int BH   = B_ * H_;     // 64
constexpr int NTOK = B_ * L_;     // 8192

// fp32 scratch
__device__ float g_Q[BH * L_ * D_];
// packed bf16 hi/lo operands
__device__ uint32_t g_inh[3 * NTOK * E_ / 2], g_inl[3 * NTOK * E_ / 2];
__device__ uint32_t g_Wh[4 * E_ * E_ / 2],   g_Wl[4 * E_ * E_ / 2];
__device__ uint32_t g_Khg[BH * L_ * D_ / 2], g_Klg[BH * L_ * D_ / 2];
__device__ uint32_t g_Vph[BH * D_ * L_ / 2], g_Vpl[BH * D_ * L_ / 2];
__device__ uint32_t g_Ohh[BH * L_ * D_ / 2], g_Ohl[BH * L_ * D_ / 2];

// ---------------------------------------------------------------------------
__device__ __forceinline__ uint32_t pack2(float x0, float x1) {
    uint32_t r;
    asm("cvt.rn.bf16x2.f32 %0, %1, %2;" : "=r"(r) : "f"(x1), "f"(x0));
    return r;
}
__device__ __forceinline__ void split_pack(float x0, float x1,
                                           uint32_t& h, uint32_t& l) {
    h = pack2(x0, x1);
    float h0 = __uint_as_float(h << 16);
    float h1 = __uint_as_float(h & 0xffff0000u);
    l = pack2(x0 - h0, x1 - h1);
}
__device__ __forceinline__ void mma_bf16(float* c, const uint32_t* a,
                                         const uint32_t* b) {
    asm volatile(
        "mma.sync.aligned.m16n8k16.row.col.f32.bf16.bf16.f32 "
        "{%0,%1,%2,%3}, {%4,%5,%6,%7}, {%8,%9}, {%0,%1,%2,%3};"
        : "+f"(c[0]), "+f"(c[1]), "+f"(c[2]), "+f"(c[3])
        : "r"(a[0]), "r"(a[1]), "r"(a[2]), "r"(a[3]), "r"(b[0]), "r"(b[1]));
}
__device__ __forceinline__ void ldm4(uint32_t* r, uint32_t a) {
    asm volatile("ldmatrix.sync.aligned.m8n8.x4.shared.b16 {%0,%1,%2,%3}, [%4];"
        : "=r"(r[0]), "=r"(r[1]), "=r"(r[2]), "=r"(r[3]) : "r"(a));
}
__device__ __forceinline__ uint32_t smem_u32(const void* p) {
    uint32_t a;
    asm("{ .reg .u64 t; cvta.to.shared.u64 t, %1; cvt.u32.u64 %0, t; }"
        : "=r"(a) : "l"(p));
    return a;
}
__device__ __forceinline__ void cp16(uint32_t dst, const void* src) {
    asm volatile("cp.async.cg.shared.global [%0], [%1], 16;"
                 :: "r"(dst), "l"(src) : "memory");
}
__device__ __forceinline__ void cp_commit() {
    asm volatile("cp.async.commit_group;" ::: "memory");
}
__device__ __forceinline__ void cp_wait0() {
    asm volatile("cp.async.wait_group 0;" ::: "memory");
}
__device__ __forceinline__ void cp_wait2() {
    asm volatile("cp.async.wait_group 2;" ::: "memory");
}

// ---------------------------------------------------------------------------
// prep: pack input z and W z (z==2 also packs Wo) into bf16 hi/lo.
// ---------------------------------------------------------------------------
constexpr int IN8 = NTOK * E_ / 8;
constexpr int W8  = E_ * E_ / 8;

__global__ __launch_bounds__(256) void pack_combo(
    const float4* __restrict__ in_src, const float4* __restrict__ w_src,
    const float4* __restrict__ w2_src, int z)
{
    int g = blockIdx.x * 256 + threadIdx.x;
    const float4* src; uint4* dh; uint4* dl; int idx;
    if (g < IN8) {
        src = in_src; idx = g;
        dh = (uint4*)g_inh + (size_t)z * IN8 + idx;
        dl = (uint4*)g_inl + (size_t)z * IN8 + idx;
    } else if (g < IN8 + W8) {
        src = w_src; idx = g - IN8;
        dh = (uint4*)g_Wh + (size_t)z * W8 + idx;
        dl = (uint4*)g_Wl + (size_t)z * W8 + idx;
    } else if (w2_src != nullptr && g < IN8 + 2 * W8) {
        src = w2_src; idx = g - IN8 - W8;
        dh = (uint4*)g_Wh + (size_t)3 * W8 + idx;
        dl = (uint4*)g_Wl + (size_t)3 * W8 + idx;
    } else return;
    float4 a = src[2 * idx], b = src[2 * idx + 1];
    uint4 h, l;
    split_pack(a.x, a.y, h.x, l.x);
    split_pack(a.z, a.w, h.y, l.y);
    split_pack(b.x, b.y, h.z, l.z);
    split_pack(b.z, b.w, h.w, l.w);
    *dh = h; *dl = l;
}

// empty pad kernel: keeps attn_tc at ncu's -s 5 capture slot
__global__ void profile_pad() {}

// ---------------------------------------------------------------------------
// 3xBF16 GEMM body, BK=32, 4-stage pipeline, stride 20 words (conflict-free).
// ---------------------------------------------------------------------------
constexpr int NKC2 = E_ / 32;     // 32 chunks
constexpr int PSTR2 = 20;
constexpr int ARR_B = 128 * PSTR2 * 4;             // 10240 per array
constexpr int STAGE_B = 4 * ARR_B;                 // 40960
constexpr int NSTAGE = 4;
constexpr int GEMM_SMEM = NSTAGE * STAGE_B;        // 163840 (1 CTA/SM)

__device__ __forceinline__ uint32_t a_lane_off(int lane) {
    int row = (lane & 7) + ((lane >> 3) & 1) * 8;
    int cw  = (lane >> 4) * 4;
    return (uint32_t)((row * PSTR2 + cw) * 4);
}
__device__ __forceinline__ uint32_t b_lane_off(int lane) {
    int row = (lane & 7) + (lane >> 4) * 8;
    int cw  = ((lane >> 3) & 1) * 4;
    return (uint32_t)((row * PSTR2 + cw) * 4);
}

__device__ __forceinline__ void mma_chunk32(uint32_t stage, int wm, int wn,
                                            uint32_t aoff, uint32_t boff,
                                            float acc[4][4][4]) {
#pragma unroll
    for (int kc2 = 0; kc2 < 2; kc2++) {
        const uint32_t ko = kc2 * 32;
        uint32_t ah[4][4], al[4][4], bh[4][2], bl[4][2];
#pragma unroll
        for (int i = 0; i < 4; i++) {
            uint32_t addr = stage + (uint32_t)((wm + 16 * i) * PSTR2 * 4) + aoff + ko;
            ldm4(ah[i], addr);
            ldm4(al[i], addr + ARR_B);
        }
#pragma unroll
        for (int jp = 0; jp < 2; jp++) {
            uint32_t addr = stage + 2 * ARR_B +
                            (uint32_t)((wn + 16 * jp) * PSTR2 * 4) + boff + ko;
            uint32_t th[4], tl[4];
            ldm4(th, addr);
            ldm4(tl, addr + ARR_B);
            bh[2 * jp][0] = th[0]; bh[2 * jp][1] = th[1];
            bh[2 * jp + 1][0] = th[2]; bh[2 * jp + 1][1] = th[3];
            bl[2 * jp][0] = tl[0]; bl[2 * jp][1] = tl[1];
            bl[2 * jp + 1][0] = tl[2]; bl[2 * jp + 1][1] = tl[3];
        }
#pragma unroll
        for (int j = 0; j < 4; j++)
#pragma unroll
            for (int i = 0; i < 4; i++) {
                mma_bf16(acc[i][j], ah[i], bh[j]);
                mma_bf16(acc[i][j], ah[i], bl[j]);
                mma_bf16(acc[i][j], al[i], bh[j]);
            }
    }
}

// ---------------------------------------------------------------------------
// Projection GEMM (BK=32, 4-stage). z: 0=Q (fp32), 1=K (packed),
// 2=V (transposed-packed directly in epilogue via shfl row-pair exchange).
// ---------------------------------------------------------------------------
__global__ __launch_bounds__(256, 1) void proj_tc()
{
    extern __shared__ uint8_t gsm_raw[];
    const uint32_t sb = smem_u32(gsm_raw);
    const int z = blockIdx.z;
    const uint32_t* Xh = g_inh + (size_t)z * (NTOK * E_ / 2);
    const uint32_t* Xl = g_inl + (size_t)z * (NTOK * E_ / 2);
    const uint32_t* WhP = g_Wh + (size_t)z * (E_ * E_ / 2);
    const uint32_t* WlP = g_Wl + (size_t)z * (E_ * E_ / 2);

    const int tid = threadIdx.x, wid = tid >> 5, lane = tid & 31;
    const int gr = lane >> 2, tig = lane & 3;
    const int wm = (wid & 1) * 64, wn = (wid >> 1) * 32;
    const int m0 = blockIdx.y * 128, n0 = blockIdx.x * 128;
    const uint32_t aoff = a_lane_off(lane), boff = b_lane_off(lane);

    const int row = tid >> 1, half = tid & 1;
    const size_t srcA = (size_t)(m0 + row) * (E_ / 2) + half * 8;
    const size_t srcB = (size_t)(n0 + row) * (E_ / 2) + half * 8;
    const uint32_t dOff = (uint32_t)(row * PSTR2 + half * 8) * 4;

    // issue chunk kc (empty commit past the end keeps group count uniform)
    auto issue = [&](int kc) {
        if (kc < NKC2) {
            const uint32_t base = sb + (kc & (NSTAGE - 1)) * STAGE_B;
            const size_t o = (size_t)kc * 16;
            cp16(base + dOff,                Xh + srcA + o);
            cp16(base + dOff + 16,           Xh + srcA + o + 4);
            cp16(base + ARR_B + dOff,        Xl + srcA + o);
            cp16(base + ARR_B + dOff + 16,   Xl + srcA + o + 4);
            cp16(base + 2 * ARR_B + dOff,      WhP + srcB + o);
            cp16(base + 2 * ARR_B + dOff + 16, WhP + srcB + o + 4);
            cp16(base + 3 * ARR_B + dOff,      WlP + srcB + o);
            cp16(base + 3 * ARR_B + dOff + 16, WlP + srcB + o + 4);
        }
        cp_commit();
    };
    issue(0); issue(1); issue(2);

    float acc[4][4][4] = {};
    for (int kc = 0; kc < NKC2; kc++) {
        cp_wait2();            // oldest group (kc) landed
        __syncthreads();       // all warps done with stage (kc+3)&3 from kc-1
        issue(kc + 3);
        mma_chunk32(sb + (kc & (NSTAGE - 1)) * STAGE_B, wm, wn, aoff, boff, acc);
    }

#pragma unroll
    for (int i = 0; i < 4; i++) {
        const int m_a = m0 + wm + 16 * i + gr;
        const int m_b = m_a + 8;
        const int ba = m_a >> 11, la = m_a & (L_ - 1);
        const int bb = m_b >> 11, lb = m_b & (L_ - 1);
#pragma unroll
        for (int j = 0; j < 4; j++) {
            const int col = n0 + wn + 8 * j + 2 * tig;
            const int hg = col >> 6, d = col & 63;
            if (z == 0) {
                *(float2*)&g_Q[((size_t)(ba * H_ + hg) * L_ + la) * D_ + d] =
                    make_float2(acc[i][j][0], acc[i][j][1]);
                *(float2*)&g_Q[((size_t)(bb * H_ + hg) * L_ + lb) * D_ + d] =
                    make_float2(acc[i][j][2], acc[i][j][3]);
            } else if (z == 1) {
                uint32_t ph, pl;
                size_t ia = ((size_t)(ba * H_ + hg) * L_ + la) * 32 + (d >> 1);
                split_pack(acc[i][j][0], acc[i][j][1], ph, pl);
                g_Khg[ia] = ph; g_Klg[ia] = pl;
                size_t ib = ((size_t)(bb * H_ + hg) * L_ + lb) * 32 + (d >> 1);
                split_pack(acc[i][j][2], acc[i][j][3], ph, pl);
                g_Khg[ib] = ph; g_Klg[ib] = pl;
            } else {
                // V: transposed-packed write via shfl_xor(4) row-pair exchange
                float o0 = __shfl_xor_sync(0xffffffffu, acc[i][j][0], 4);
                float o1 = __shfl_xor_sync(0xffffffffu, acc[i][j][1], 4);
                float o2 = __shfl_xor_sync(0xffffffffu, acc[i][j][2], 4);
                float o3 = __shfl_xor_sync(0xffffffffu, acc[i][j][3], 4);
                uint32_t h, l;
                if ((gr & 1) == 0) {
                    const int bhd = (ba * H_ + hg) * 64;
                    size_t i0 = (size_t)(bhd + d) * (L_ / 2) + (la >> 1);
                    split_pack(acc[i][j][0], o0, h, l);
                    g_Vph[i0] = h; g_Vpl[i0] = l;
                    size_t i1 = (size_t)(bhd + d + 1) * (L_ / 2) + (la >> 1);
                    split_pack(acc[i][j][1], o1, h, l);
                    g_Vph[i1] = h; g_Vpl[i1] = l;
                } else {
                    const int bhd = (bb * H_ + hg) * 64;
                    size_t i0 = (size_t)(bhd + d) * (L_ / 2) + ((lb - 1) >> 1);
                    split_pack(o2, acc[i][j][2], h, l);
                    g_Vph[i0] = h; g_Vpl[i0] = l;
                    size_t i1 = (size_t)(bhd + d + 1) * (L_ / 2) + ((lb - 1) >> 1);
                    split_pack(o3, acc[i][j][3], h, l);
                    g_Vph[i1] = h; g_Vpl[i1] = l;
                }
            }
        }
    }
}

// ---------------------------------------------------------------------------
// Output projection (BK=32, 4-stage): A = packed Oh, B = packed Wo.
// ---------------------------------------------------------------------------
__global__ __launch_bounds__(256, 1) void outproj_tc(float* __restrict__ out)
{
    extern __shared__ uint8_t gsm_raw[];
    const uint32_t sb = smem_u32(gsm_raw);
    const uint32_t* WhP = g_Wh + (size_t)3 * (E_ * E_ / 2);
    const uint32_t* WlP = g_Wl + (size_t)3 * (E_ * E_ / 2);

    const int tid = threadIdx.x, wid = tid >> 5, lane = tid & 31;
    const int gr = lane >> 2, tig = lane & 3;
    const int wm = (wid & 1) * 64, wn = (wid >> 1) * 32;
    const int m0 = blockIdx.y * 128, n0 = blockIdx.x * 128;
    const uint32_t aoff = a_lane_off(lane), boff = b_lane_off(lane);

    const int row = tid >> 1, half = tid & 1;
    const int m = m0 + row, bb_ = m >> 11, ll = m & (L_ - 1);
    const size_t srcB = (size_t)(n0 + row) * (E_ / 2) + half * 8;
    const uint32_t dOff = (uint32_t)(row * PSTR2 + half * 8) * 4;

    auto issue = [&](int kc) {
        if (kc < NKC2) {
            const uint32_t base = sb + (kc & (NSTAGE - 1)) * STAGE_B;
            const int hg = kc >> 1;
            const int w0 = (kc & 1) * 16 + half * 8;
            const size_t sa = ((size_t)(bb_ * H_ + hg) * L_ + ll) * 32 + w0;
            const size_t ob = (size_t)kc * 16;
            cp16(base + dOff,                g_Ohh + sa);
            cp16(base + dOff + 16,           g_Ohh + sa + 4);
            cp16(base + ARR_B + dOff,        g_Ohl + sa);
            cp16(base + ARR_B + dOff + 16,   g_Ohl + sa + 4);
            cp16(base + 2 * ARR_B + dOff,      WhP + srcB + ob);
            cp16(base + 2 * ARR_B + dOff + 16, WhP + srcB + ob + 4);
            cp16(base + 3 * ARR_B + dOff,      WlP + srcB + ob);
            cp16(base + 3 * ARR_B + dOff + 16, WlP + srcB + ob + 4);
        }
        cp_commit();
    };
    issue(0); issue(1); issue(2);

    float acc[4][4][4] = {};
    for (int kc = 0; kc < NKC2; kc++) {
        cp_wait2();
        __syncthreads();
        issue(kc + 3);
        mma_chunk32(sb + (kc & (NSTAGE - 1)) * STAGE_B, wm, wn, aoff, boff, acc);
    }

#pragma unroll
    for (int i = 0; i < 4; i++) {
        const int m_a = m0 + wm + 16 * i + gr;
#pragma unroll
        for (int j = 0; j < 4; j++) {
            const int col = n0 + wn + 8 * j + 2 * tig;
            *(float2*)&out[(size_t)m_a * E_ + col] =
                make_float2(acc[i][j][0], acc[i][j][1]);
            *(float2*)&out[(size_t)(m_a + 8) * E_ + col] =
                make_float2(acc[i][j][2], acc[i][j][3]);
        }
    }
}

// ---------------------------------------------------------------------------
// Tensor-core fused causal attention (unchanged from R15/R13 best form).
// ---------------------------------------------------------------------------
__global__ __launch_bounds__(256, 2) void attn_tc(float* __restrict__ attn_base)
{
    extern __shared__ uint32_t usm[];
    const uint32_t sb = smem_u32(usm);
    uint32_t* P2h = usm + 18432;
    uint32_t* P2l = usm + 23040;
    float*    sl  = (float*)(usm + 27648);

    const int bh = blockIdx.y;
    const int it = (int)gridDim.x - 1 - (int)blockIdx.x;   // heavy tiles first
    const int q0 = it * 128;
    const int tid = threadIdx.x, wid = tid >> 5, lane = tid & 31;
    const int gr = lane >> 2, tig = lane & 3;
    const int wm = wid * 16;

    const float* Qp = g_Q + (size_t)bh * L_ * D_;
    float* attn = attn_base + (size_t)bh * L_ * L_;

    const uint32_t kvoff = (uint32_t)(((8 * (lane >> 4) + (lane & 7)) * 36 +
                                       ((lane >> 3) & 1) * 4) * 4);
    const uint32_t poff  = (uint32_t)(((wm + (lane & 7) + 8 * ((lane >> 3) & 1)) * 36 +
                                       (lane >> 4) * 4) * 4);
    const uint32_t p2h_b = sb + 18432 * 4, p2l_b = sb + 23040 * 4;

    const int ntiles = 2 * it + 2;
    const float scale = 0.125f;

    auto issue = [&](int jt) {
        const uint32_t kbase = sb + (jt & 1) * 36864;
#pragma unroll
        for (int c = 0; c < 2; c++) {
            int s = c * 256 + tid;
            int r = s >> 3, seg = (s & 7) * 4;
            uint32_t doff = (uint32_t)(r * 36 + seg) * 4;
            size_t ksrc = ((size_t)bh * L_ + jt * 64 + r) * 32 + seg;
            size_t vsrc = ((size_t)bh * 64 + r) * (L_ / 2) + jt * 32 + seg;
            cp16(kbase + doff,         g_Khg + ksrc);
            cp16(kbase + 9216 + doff,  g_Klg + ksrc);
            cp16(kbase + 18432 + doff, g_Vph + vsrc);
            cp16(kbase + 27648 + doff, g_Vpl + vsrc);
        }
        cp_commit();
    };
    issue(0);

    // Q A-fragments, pre-split packed bf16x2
    uint32_t qh[4][4], ql[4][4];
    const int grow0 = q0 + wm + gr, grow1 = grow0 + 8;
#pragma unroll
    for (int kc = 0; kc < 4; kc++) {
        float2 q00 = *(const float2*)&Qp[(size_t)grow0 * D_ + kc * 16 + 2 * tig];
        float2 q10 = *(const float2*)&Qp[(size_t)grow1 * D_ + kc * 16 + 2 * tig];
        float2 q01 = *(const float2*)&Qp[(size_t)grow0 * D_ + kc * 16 + 2 * tig + 8];
        float2 q11 = *(const float2*)&Qp[(size_t)grow1 * D_ + kc * 16 + 2 * tig + 8];
        split_pack(q00.x, q00.y, qh[kc][0], ql[kc][0]);
        split_pack(q10.x, q10.y, qh[kc][1], ql[kc][1]);
        split_pack(q01.x, q01.y, qh[kc][2], ql[kc][2]);
        split_pack(q11.x, q11.y, qh[kc][3], ql[kc][3]);
    }

    // zero-fill upper triangle EARLY: stores drain behind the mainloop
    {
        const float4 z4 = make_float4(0.f, 0.f, 0.f, 0.f);
        for (int j2 = ntiles; j2 < L_ / 64; j2++) {
#pragma unroll
            for (int c = 0; c < 8; c++) {
                int id = c * 256 + tid;
                int r = id >> 4, c4 = (id & 15) << 2;
                *(float4*)&attn[(size_t)(q0 + r) * L_ + j2 * 64 + c4] = z4;
            }
        }
    }

    float l0 = 0.f, l1 = 0.f;
    float oa[8][4] = {};

    for (int jt = 0; jt < ntiles; jt++) {
        cp_wait0();
        __syncthreads();
        if (jt + 1 < ntiles) issue(jt + 1);

        const uint32_t kh_b = sb + (jt & 1) * 36864;
        const uint32_t kl_b = kh_b + 9216;
        const uint32_t vh_b = kh_b + 18432;
        const uint32_t vl_b = kh_b + 27648;

        // QK + exp fused, nt-pairs
#pragma unroll
        for (int np = 0; np < 4; np++) {
            float sc[2][4] = {};
            const uint32_t rowb = (uint32_t)(16 * np * 36 * 4) + kvoff;
#pragma unroll
            for (int kc = 0; kc < 4; kc++) {
                uint32_t kh4[4], kl4[4];
                ldm4(kh4, kh_b + rowb + kc * 32);
                ldm4(kl4, kl_b + rowb + kc * 32);
                mma_bf16(sc[0], qh[kc], kh4);
                mma_bf16(sc[0], qh[kc], kl4);
                mma_bf16(sc[0], ql[kc], kh4);
                mma_bf16(sc[1], qh[kc], kh4 + 2);
                mma_bf16(sc[1], qh[kc], kl4 + 2);
                mma_bf16(sc[1], ql[kc], kh4 + 2);
            }
#pragma unroll
            for (int u = 0; u < 2; u++) {
                const int nt = 2 * np + u;
                int jc = jt * 64 + nt * 8 + 2 * tig;
                float p0 = __expf(sc[u][0] * scale); if (jc     > grow0) p0 = 0.f;
                float p1 = __expf(sc[u][1] * scale); if (jc + 1 > grow0) p1 = 0.f;
                float p2 = __expf(sc[u][2] * scale); if (jc     > grow1) p2 = 0.f;
                float p3 = __expf(sc[u][3] * scale); if (jc + 1 > grow1) p3 = 0.f;
                l0 += p0 + p1;
                l1 += p2 + p3;
                uint32_t h, l;
                split_pack(p0, p1, h, l);
                P2h[(wm + gr) * 36 + nt * 4 + tig] = h;
                P2l[(wm + gr) * 36 + nt * 4 + tig] = l;
                split_pack(p2, p3, h, l);
                P2h[(wm + gr + 8) * 36 + nt * 4 + tig] = h;
                P2l[(wm + gr + 8) * 36 + nt * 4 + tig] = l;
                *(float2*)&attn[(size_t)grow0 * L_ + jc] = make_float2(p0, p1);
                *(float2*)&attn[(size_t)grow1 * L_ + jc] = make_float2(p2, p3);
            }
        }
        __syncwarp();   // P2 rows are warp-private

        // O += P V
#pragma unroll
        for (int kc = 0; kc < 4; kc++) {
            uint32_t ph[4], plo[4];
            ldm4(ph,  p2h_b + poff + kc * 32);
            ldm4(plo, p2l_b + poff + kc * 32);
#pragma unroll
            for (int np = 0; np < 4; np++) {
                const uint32_t rowb = (uint32_t)(16 * np * 36 * 4) + kvoff;
                uint32_t vh4[4], vl4[4];
                ldm4(vh4, vh_b + rowb + kc * 32);
                ldm4(vl4, vl_b + rowb + kc * 32);
                mma_bf16(oa[2 * np], ph, vh4);
                mma_bf16(oa[2 * np], ph, vl4);
                mma_bf16(oa[2 * np], plo, vh4);
                mma_bf16(oa[2 * np + 1], ph, vh4 + 2);
                mma_bf16(oa[2 * np + 1], ph, vl4 + 2);
                mma_bf16(oa[2 * np + 1], plo, vh4 + 2);
            }
        }
    }

    // row sums: reduce lane partials over the quad
    l0 += __shfl_xor_sync(0xffffffffu, l0, 1);
    l0 += __shfl_xor_sync(0xffffffffu, l0, 2);
    l1 += __shfl_xor_sync(0xffffffffu, l1, 1);
    l1 += __shfl_xor_sync(0xffffffffu, l1, 2);
    const float inv0 = 1.f / l0, inv1 = 1.f / l1;
    if (tig == 0) {
        sl[wm + gr] = inv0;
        sl[wm + gr + 8] = inv1;
    }
    // normalized O -> packed global (feeds outproj cp.async)
#pragma unroll
    for (int nt = 0; nt < 8; nt++) {
        uint32_t h, l;
        split_pack(oa[nt][0] * inv0, oa[nt][1] * inv0, h, l);
        size_t ia = ((size_t)bh * L_ + grow0) * 32 + nt * 4 + tig;
        g_Ohh[ia] = h; g_Ohl[ia] = l;
        split_pack(oa[nt][2] * inv1, oa[nt][3] * inv1, h, l);
        size_t ib = ((size_t)bh * L_ + grow1) * 32 + nt * 4 + tig;
        g_Ohh[ib] = h; g_Ohl[ib] = l;
    }
    __syncthreads();   // sl visible; all P gmem writes done CTA-wide

    // normalize lower tiles in place, most-recently-written (L2-hot) first
    for (int j2 = ntiles - 1; j2 >= 0; j2--) {
#pragma unroll
        for (int c = 0; c < 8; c++) {
            int id = c * 256 + tid;
            int r = id >> 4, c4 = (id & 15) << 2;
            float inv = sl[r];
            float* p = &attn[(size_t)(q0 + r) * L_ + j2 * 64 + c4];
            float4 v = *(float4*)p;
            v.x *= inv; v.y *= inv; v.z *= inv; v.w *= inv;
            *(float4*)p = v;
        }
    }
}

constexpr int ATTN_SMEM = (27648 + 128) * 4;   // 111104 B

// ---------------------------------------------------------------------------
extern "C" void kernel_launch(void* const* d_in, const int* in_sizes, int n_in,
                              void* d_out, int out_size)
{
    const float* qkv[3] = {nullptr, nullptr, nullptr};
    const float* Ws[4]  = {nullptr, nullptr, nullptr, nullptr};
    int nqkv = 0, nw = 0;
    for (int i = 0; i < n_in; i++) {
        if (in_sizes[i] == NTOK * E_) { if (nqkv < 3) qkv[nqkv++] = (const float*)d_in[i]; }
        else if (in_sizes[i] == E_ * E_) { if (nw < 4) Ws[nw++] = (const float*)d_in[i]; }
    }
    float* out  = (float*)d_out;
    float* attn = out + (size_t)B_ * L_ * E_;

    cudaFuncSetAttribute(proj_tc, cudaFuncAttributeMaxDynamicSharedMemorySize, GEMM_SMEM);
    cudaFuncSetAttribute(outproj_tc, cudaFuncAttributeMaxDynamicSharedMemorySize, GEMM_SMEM);
    cudaFuncSetAttribute(attn_tc, cudaFuncAttributeMaxDynamicSharedMemorySize, ATTN_SMEM);

    pack_combo<<<(IN8 + W8 + 255) / 256, 256>>>(
        (const float4*)qkv[0], (const float4*)Ws[0], nullptr, 0);
    pack_combo<<<(IN8 + W8 + 255) / 256, 256>>>(
        (const float4*)qkv[1], (const float4*)Ws[1], nullptr, 1);
    pack_combo<<<(IN8 + 2 * W8 + 255) / 256, 256>>>(
        (const float4*)qkv[2], (const float4*)Ws[2], (const float4*)Ws[3], 2);

    proj_tc<<<dim3(E_ / 128, NTOK / 128, 3), 256, GEMM_SMEM>>>();
    profile_pad<<<1, 32>>>();   // keeps attn_tc at ncu -s 5 slot
    attn_tc<<<dim3(L_ / 128, BH), 256, ATTN_SMEM>>>(attn);
    outproj_tc<<<dim3(E_ / 128, NTOK / 128), 256, GEMM_SMEM>>>(out);
}

// round 17
// speedup vs baseline: 1.1620x; 1.1620x over previous
#include <cuda_runtime.h>
#include <cstdint>

// ---------------------------------------------------------------------------
// MHA forward: out = (softmax_causal(QK^T/sqrt(D)) V) Wo^T,  also emit attn.
// B=4, L=2048, E=1024, H=16, D=64.
// d_out layout: [out: B*L*E floats][attn: B*H*L*L floats]
// 3xBF16 m16n8k16 everywhere; operands pre-packed bf16 hi/lo in gmem;
// ldmatrix fragment loads; BK=32 2-stage GEMMs (R15 optimum, restored).
// R17: attention TWO-PASS: pass A computes row sums l (QK+exp only, K-only
// cp.async); pass B recomputes QK+exp, scales by 1/l at generation, writes
// FINAL normalized P once (no post normalize pass: 2.14GB -> 1.07GB traffic).
// ---------------------------------------------------------------------------

constexpr int B_ = 4, L_ = 2048, E_ = 1024, H_ = 16, D_ = 64;
constexpr int BH   = B_ * H_;     // 64
constexpr int NTOK = B_ * L_;     // 8192

// fp32 scratch
__device__ float g_Q[BH * L_ * D_];
// packed bf16 hi/lo operands
__device__ uint32_t g_inh[3 * NTOK * E_ / 2], g_inl[3 * NTOK * E_ / 2];
__device__ uint32_t g_Wh[4 * E_ * E_ / 2],   g_Wl[4 * E_ * E_ / 2];
__device__ uint32_t g_Khg[BH * L_ * D_ / 2], g_Klg[BH * L_ * D_ / 2];
__device__ uint32_t g_Vph[BH * D_ * L_ / 2], g_Vpl[BH * D_ * L_ / 2];
__device__ uint32_t g_Ohh[BH * L_ * D_ / 2], g_Ohl[BH * L_ * D_ / 2];

// ---------------------------------------------------------------------------
__device__ __forceinline__ uint32_t pack2(float x0, float x1) {
    uint32_t r;
    asm("cvt.rn.bf16x2.f32 %0, %1, %2;" : "=r"(r) : "f"(x1), "f"(x0));
    return r;
}
__device__ __forceinline__ void split_pack(float x0, float x1,
                                           uint32_t& h, uint32_t& l) {
    h = pack2(x0, x1);
    float h0 = __uint_as_float(h << 16);
    float h1 = __uint_as_float(h & 0xffff0000u);
    l = pack2(x0 - h0, x1 - h1);
}
__device__ __forceinline__ void mma_bf16(float* c, const uint32_t* a,
                                         const uint32_t* b) {
    asm volatile(
        "mma.sync.aligned.m16n8k16.row.col.f32.bf16.bf16.f32 "
        "{%0,%1,%2,%3}, {%4,%5,%6,%7}, {%8,%9}, {%0,%1,%2,%3};"
        : "+f"(c[0]), "+f"(c[1]), "+f"(c[2]), "+f"(c[3])
        : "r"(a[0]), "r"(a[1]), "r"(a[2]), "r"(a[3]), "r"(b[0]), "r"(b[1]));
}
__device__ __forceinline__ void ldm4(uint32_t* r, uint32_t a) {
    asm volatile("ldmatrix.sync.aligned.m8n8.x4.shared.b16 {%0,%1,%2,%3}, [%4];"
        : "=r"(r[0]), "=r"(r[1]), "=r"(r[2]), "=r"(r[3]) : "r"(a));
}
__device__ __forceinline__ uint32_t smem_u32(const void* p) {
    uint32_t a;
    asm("{ .reg .u64 t; cvta.to.shared.u64 t, %1; cvt.u32.u64 %0, t; }"
        : "=r"(a) : "l"(p));
    return a;
}
__device__ __forceinline__ void cp16(uint32_t dst, const void* src) {
    asm volatile("cp.async.cg.shared.global [%0], [%1], 16;"
                 :: "r"(dst), "l"(src) : "memory");
}
__device__ __forceinline__ void cp_commit() {
    asm volatile("cp.async.commit_group;" ::: "memory");
}
__device__ __forceinline__ void cp_wait0() {
    asm volatile("cp.async.wait_group 0;" ::: "memory");
}

// ---------------------------------------------------------------------------
// prep: pack input z and W z (z==2 also packs Wo) into bf16 hi/lo.
// ---------------------------------------------------------------------------
constexpr int IN8 = NTOK * E_ / 8;
constexpr int W8  = E_ * E_ / 8;

__global__ __launch_bounds__(256) void pack_combo(
    const float4* __restrict__ in_src, const float4* __restrict__ w_src,
    const float4* __restrict__ w2_src, int z)
{
    int g = blockIdx.x * 256 + threadIdx.x;
    const float4* src; uint4* dh; uint4* dl; int idx;
    if (g < IN8) {
        src = in_src; idx = g;
        dh = (uint4*)g_inh + (size_t)z * IN8 + idx;
        dl = (uint4*)g_inl + (size_t)z * IN8 + idx;
    } else if (g < IN8 + W8) {
        src = w_src; idx = g - IN8;
        dh = (uint4*)g_Wh + (size_t)z * W8 + idx;
        dl = (uint4*)g_Wl + (size_t)z * W8 + idx;
    } else if (w2_src != nullptr && g < IN8 + 2 * W8) {
        src = w2_src; idx = g - IN8 - W8;
        dh = (uint4*)g_Wh + (size_t)3 * W8 + idx;
        dl = (uint4*)g_Wl + (size_t)3 * W8 + idx;
    } else return;
    float4 a = src[2 * idx], b = src[2 * idx + 1];
    uint4 h, l;
    split_pack(a.x, a.y, h.x, l.x);
    split_pack(a.z, a.w, h.y, l.y);
    split_pack(b.x, b.y, h.z, l.z);
    split_pack(b.z, b.w, h.w, l.w);
    *dh = h; *dl = l;
}

// ---------------------------------------------------------------------------
// 3xBF16 GEMM body, BK=32, 2-stage ping-pong (R15 optimum), stride 20 words.
// ---------------------------------------------------------------------------
constexpr int NKC2 = E_ / 32;     // 32 chunks
constexpr int PSTR2 = 20;
constexpr int ARR_B = 128 * PSTR2 * 4;             // 10240 per array
constexpr int STAGE_B = 4 * ARR_B;                 // 40960
constexpr int GEMM_SMEM = 2 * STAGE_B;             // 81920 (2 CTA/SM)

__device__ __forceinline__ uint32_t a_lane_off(int lane) {
    int row = (lane & 7) + ((lane >> 3) & 1) * 8;
    int cw  = (lane >> 4) * 4;
    return (uint32_t)((row * PSTR2 + cw) * 4);
}
__device__ __forceinline__ uint32_t b_lane_off(int lane) {
    int row = (lane & 7) + (lane >> 4) * 8;
    int cw  = ((lane >> 3) & 1) * 4;
    return (uint32_t)((row * PSTR2 + cw) * 4);
}

__device__ __forceinline__ void mma_chunk32(uint32_t stage, int wm, int wn,
                                            uint32_t aoff, uint32_t boff,
                                            float acc[4][4][4]) {
#pragma unroll
    for (int kc2 = 0; kc2 < 2; kc2++) {
        const uint32_t ko = kc2 * 32;
        uint32_t ah[4][4], al[4][4], bh[4][2], bl[4][2];
#pragma unroll
        for (int i = 0; i < 4; i++) {
            uint32_t addr = stage + (uint32_t)((wm + 16 * i) * PSTR2 * 4) + aoff + ko;
            ldm4(ah[i], addr);
            ldm4(al[i], addr + ARR_B);
        }
#pragma unroll
        for (int jp = 0; jp < 2; jp++) {
            uint32_t addr = stage + 2 * ARR_B +
                            (uint32_t)((wn + 16 * jp) * PSTR2 * 4) + boff + ko;
            uint32_t th[4], tl[4];
            ldm4(th, addr);
            ldm4(tl, addr + ARR_B);
            bh[2 * jp][0] = th[0]; bh[2 * jp][1] = th[1];
            bh[2 * jp + 1][0] = th[2]; bh[2 * jp + 1][1] = th[3];
            bl[2 * jp][0] = tl[0]; bl[2 * jp][1] = tl[1];
            bl[2 * jp + 1][0] = tl[2]; bl[2 * jp + 1][1] = tl[3];
        }
#pragma unroll
        for (int j = 0; j < 4; j++)
#pragma unroll
            for (int i = 0; i < 4; i++) {
                mma_bf16(acc[i][j], ah[i], bh[j]);
                mma_bf16(acc[i][j], ah[i], bl[j]);
                mma_bf16(acc[i][j], al[i], bh[j]);
            }
    }
}

// ---------------------------------------------------------------------------
// Projection GEMM (BK=32, 2-stage). z: 0=Q (fp32), 1=K (packed),
// 2=V (transposed-packed directly in epilogue via shfl row-pair exchange).
// ---------------------------------------------------------------------------
__global__ __launch_bounds__(256, 2) void proj_tc()
{
    extern __shared__ uint8_t gsm_raw[];
    const uint32_t sb = smem_u32(gsm_raw);
    const int z = blockIdx.z;
    const uint32_t* Xh = g_inh + (size_t)z * (NTOK * E_ / 2);
    const uint32_t* Xl = g_inl + (size_t)z * (NTOK * E_ / 2);
    const uint32_t* WhP = g_Wh + (size_t)z * (E_ * E_ / 2);
    const uint32_t* WlP = g_Wl + (size_t)z * (E_ * E_ / 2);

    const int tid = threadIdx.x, wid = tid >> 5, lane = tid & 31;
    const int gr = lane >> 2, tig = lane & 3;
    const int wm = (wid & 1) * 64, wn = (wid >> 1) * 32;
    const int m0 = blockIdx.y * 128, n0 = blockIdx.x * 128;
    const uint32_t aoff = a_lane_off(lane), boff = b_lane_off(lane);

    const int row = tid >> 1, half = tid & 1;
    const size_t srcA = (size_t)(m0 + row) * (E_ / 2) + half * 8;
    const size_t srcB = (size_t)(n0 + row) * (E_ / 2) + half * 8;
    const uint32_t dOff = (uint32_t)(row * PSTR2 + half * 8) * 4;

    auto issue = [&](int kc) {
        const uint32_t base = sb + (kc & 1) * STAGE_B;
        const size_t o = (size_t)kc * 16;
        cp16(base + dOff,                Xh + srcA + o);
        cp16(base + dOff + 16,           Xh + srcA + o + 4);
        cp16(base + ARR_B + dOff,        Xl + srcA + o);
        cp16(base + ARR_B + dOff + 16,   Xl + srcA + o + 4);
        cp16(base + 2 * ARR_B + dOff,      WhP + srcB + o);
        cp16(base + 2 * ARR_B + dOff + 16, WhP + srcB + o + 4);
        cp16(base + 3 * ARR_B + dOff,      WlP + srcB + o);
        cp16(base + 3 * ARR_B + dOff + 16, WlP + srcB + o + 4);
        cp_commit();
    };
    issue(0);

    float acc[4][4][4] = {};
    for (int kc = 0; kc < NKC2; kc++) {
        cp_wait0();
        __syncthreads();
        if (kc + 1 < NKC2) issue(kc + 1);
        mma_chunk32(sb + (kc & 1) * STAGE_B, wm, wn, aoff, boff, acc);
    }

#pragma unroll
    for (int i = 0; i < 4; i++) {
        const int m_a = m0 + wm + 16 * i + gr;
        const int m_b = m_a + 8;
        const int ba = m_a >> 11, la = m_a & (L_ - 1);
        const int bb = m_b >> 11, lb = m_b & (L_ - 1);
#pragma unroll
        for (int j = 0; j < 4; j++) {
            const int col = n0 + wn + 8 * j + 2 * tig;
            const int hg = col >> 6, d = col & 63;
            if (z == 0) {
                *(float2*)&g_Q[((size_t)(ba * H_ + hg) * L_ + la) * D_ + d] =
                    make_float2(acc[i][j][0], acc[i][j][1]);
                *(float2*)&g_Q[((size_t)(bb * H_ + hg) * L_ + lb) * D_ + d] =
                    make_float2(acc[i][j][2], acc[i][j][3]);
            } else if (z == 1) {
                uint32_t ph, pl;
                size_t ia = ((size_t)(ba * H_ + hg) * L_ + la) * 32 + (d >> 1);
                split_pack(acc[i][j][0], acc[i][j][1], ph, pl);
                g_Khg[ia] = ph; g_Klg[ia] = pl;
                size_t ib = ((size_t)(bb * H_ + hg) * L_ + lb) * 32 + (d >> 1);
                split_pack(acc[i][j][2], acc[i][j][3], ph, pl);
                g_Khg[ib] = ph; g_Klg[ib] = pl;
            } else {
                float o0 = __shfl_xor_sync(0xffffffffu, acc[i][j][0], 4);
                float o1 = __shfl_xor_sync(0xffffffffu, acc[i][j][1], 4);
                float o2 = __shfl_xor_sync(0xffffffffu, acc[i][j][2], 4);
                float o3 = __shfl_xor_sync(0xffffffffu, acc[i][j][3], 4);
                uint32_t h, l;
                if ((gr & 1) == 0) {
                    const int bhd = (ba * H_ + hg) * 64;
                    size_t i0 = (size_t)(bhd + d) * (L_ / 2) + (la >> 1);
                    split_pack(acc[i][j][0], o0, h, l);
                    g_Vph[i0] = h; g_Vpl[i0] = l;
                    size_t i1 = (size_t)(bhd + d + 1) * (L_ / 2) + (la >> 1);
                    split_pack(acc[i][j][1], o1, h, l);
                    g_Vph[i1] = h; g_Vpl[i1] = l;
                } else {
                    const int bhd = (bb * H_ + hg) * 64;
                    size_t i0 = (size_t)(bhd + d) * (L_ / 2) + ((lb - 1) >> 1);
                    split_pack(o2, acc[i][j][2], h, l);
                    g_Vph[i0] = h; g_Vpl[i0] = l;
                    size_t i1 = (size_t)(bhd + d + 1) * (L_ / 2) + ((lb - 1) >> 1);
                    split_pack(o3, acc[i][j][3], h, l);
                    g_Vph[i1] = h; g_Vpl[i1] = l;
                }
            }
        }
    }
}

// ---------------------------------------------------------------------------
// Output projection (BK=32, 2-stage): A = packed Oh, B = packed Wo.
// ---------------------------------------------------------------------------
__global__ __launch_bounds__(256, 2) void outproj_tc(float* __restrict__ out)
{
    extern __shared__ uint8_t gsm_raw[];
    const uint32_t sb = smem_u32(gsm_raw);
    const uint32_t* WhP = g_Wh + (size_t)3 * (E_ * E_ / 2);
    const uint32_t* WlP = g_Wl + (size_t)3 * (E_ * E_ / 2);

    const int tid = threadIdx.x, wid = tid >> 5, lane = tid & 31;
    const int gr = lane >> 2, tig = lane & 3;
    const int wm = (wid & 1) * 64, wn = (wid >> 1) * 32;
    const int m0 = blockIdx.y * 128, n0 = blockIdx.x * 128;
    const uint32_t aoff = a_lane_off(lane), boff = b_lane_off(lane);

    const int row = tid >> 1, half = tid & 1;
    const int m = m0 + row, bb_ = m >> 11, ll = m & (L_ - 1);
    const size_t srcB = (size_t)(n0 + row) * (E_ / 2) + half * 8;
    const uint32_t dOff = (uint32_t)(row * PSTR2 + half * 8) * 4;

    auto issue = [&](int kc) {
        const uint32_t base = sb + (kc & 1) * STAGE_B;
        const int hg = kc >> 1;
        const int w0 = (kc & 1) * 16 + half * 8;
        const size_t sa = ((size_t)(bb_ * H_ + hg) * L_ + ll) * 32 + w0;
        const size_t ob = (size_t)kc * 16;
        cp16(base + dOff,                g_Ohh + sa);
        cp16(base + dOff + 16,           g_Ohh + sa + 4);
        cp16(base + ARR_B + dOff,        g_Ohl + sa);
        cp16(base + ARR_B + dOff + 16,   g_Ohl + sa + 4);
        cp16(base + 2 * ARR_B + dOff,      WhP + srcB + ob);
        cp16(base + 2 * ARR_B + dOff + 16, WhP + srcB + ob + 4);
        cp16(base + 3 * ARR_B + dOff,      WlP + srcB + ob);
        cp16(base + 3 * ARR_B + dOff + 16, WlP + srcB + ob + 4);
        cp_commit();
    };
    issue(0);

    float acc[4][4][4] = {};
    for (int kc = 0; kc < NKC2; kc++) {
        cp_wait0();
        __syncthreads();
        if (kc + 1 < NKC2) issue(kc + 1);
        mma_chunk32(sb + (kc & 1) * STAGE_B, wm, wn, aoff, boff, acc);
    }

#pragma unroll
    for (int i = 0; i < 4; i++) {
        const int m_a = m0 + wm + 16 * i + gr;
#pragma unroll
        for (int j = 0; j < 4; j++) {
            const int col = n0 + wn + 8 * j + 2 * tig;
            *(float2*)&out[(size_t)m_a * E_ + col] =
                make_float2(acc[i][j][0], acc[i][j][1]);
            *(float2*)&out[(size_t)(m_a + 8) * E_ + col] =
                make_float2(acc[i][j][2], acc[i][j][3]);
        }
    }
}

// ---------------------------------------------------------------------------
// Tensor-core fused causal attention, TWO-PASS:
//  pass A: K-only cp.async, QK+exp, accumulate row sums l (no stores)
//  pass B: K+V cp.async, QK+exp, p *= 1/l, write FINAL normalized P once,
//          PV with normalized P (O needs no end scaling). No post pass.
// ---------------------------------------------------------------------------
__global__ __launch_bounds__(256, 2) void attn_tc(float* __restrict__ attn_base)
{
    extern __shared__ uint32_t usm[];
    const uint32_t sb = smem_u32(usm);
    uint32_t* P2h = usm + 18432;
    uint32_t* P2l = usm + 23040;

    const int bh = blockIdx.y;
    const int it = (int)gridDim.x - 1 - (int)blockIdx.x;   // heavy tiles first
    const int q0 = it * 128;
    const int tid = threadIdx.x, wid = tid >> 5, lane = tid & 31;
    const int gr = lane >> 2, tig = lane & 3;
    const int wm = wid * 16;

    const float* Qp = g_Q + (size_t)bh * L_ * D_;
    float* attn = attn_base + (size_t)bh * L_ * L_;

    const uint32_t kvoff = (uint32_t)(((8 * (lane >> 4) + (lane & 7)) * 36 +
                                       ((lane >> 3) & 1) * 4) * 4);
    const uint32_t poff  = (uint32_t)(((wm + (lane & 7) + 8 * ((lane >> 3) & 1)) * 36 +
                                       (lane >> 4) * 4) * 4);
    const uint32_t p2h_b = sb + 18432 * 4, p2l_b = sb + 23040 * 4;

    const int ntiles = 2 * it + 2;
    const float scale = 0.125f;

    // K-only tile fetch (pass A)
    auto issueK = [&](int jt) {
        const uint32_t kbase = sb + (jt & 1) * 36864;
#pragma unroll
        for (int c = 0; c < 2; c++) {
            int s = c * 256 + tid;
            int r = s >> 3, seg = (s & 7) * 4;
            uint32_t doff = (uint32_t)(r * 36 + seg) * 4;
            size_t ksrc = ((size_t)bh * L_ + jt * 64 + r) * 32 + seg;
            cp16(kbase + doff,        g_Khg + ksrc);
            cp16(kbase + 9216 + doff, g_Klg + ksrc);
        }
        cp_commit();
    };
    // K+V tile fetch (pass B)
    auto issue = [&](int jt) {
        const uint32_t kbase = sb + (jt & 1) * 36864;
#pragma unroll
        for (int c = 0; c < 2; c++) {
            int s = c * 256 + tid;
            int r = s >> 3, seg = (s & 7) * 4;
            uint32_t doff = (uint32_t)(r * 36 + seg) * 4;
            size_t ksrc = ((size_t)bh * L_ + jt * 64 + r) * 32 + seg;
            size_t vsrc = ((size_t)bh * 64 + r) * (L_ / 2) + jt * 32 + seg;
            cp16(kbase + doff,         g_Khg + ksrc);
            cp16(kbase + 9216 + doff,  g_Klg + ksrc);
            cp16(kbase + 18432 + doff, g_Vph + vsrc);
            cp16(kbase + 27648 + doff, g_Vpl + vsrc);
        }
        cp_commit();
    };
    issueK(0);

    // Q A-fragments, pre-split packed bf16x2
    uint32_t qh[4][4], ql[4][4];
    const int grow0 = q0 + wm + gr, grow1 = grow0 + 8;
#pragma unroll
    for (int kc = 0; kc < 4; kc++) {
        float2 q00 = *(const float2*)&Qp[(size_t)grow0 * D_ + kc * 16 + 2 * tig];
        float2 q10 = *(const float2*)&Qp[(size_t)grow1 * D_ + kc * 16 + 2 * tig];
        float2 q01 = *(const float2*)&Qp[(size_t)grow0 * D_ + kc * 16 + 2 * tig + 8];
        float2 q11 = *(const float2*)&Qp[(size_t)grow1 * D_ + kc * 16 + 2 * tig + 8];
        split_pack(q00.x, q00.y, qh[kc][0], ql[kc][0]);
        split_pack(q10.x, q10.y, qh[kc][1], ql[kc][1]);
        split_pack(q01.x, q01.y, qh[kc][2], ql[kc][2]);
        split_pack(q11.x, q11.y, qh[kc][3], ql[kc][3]);
    }

    // zero-fill upper triangle EARLY: stores drain behind the passes
    {
        const float4 z4 = make_float4(0.f, 0.f, 0.f, 0.f);
        for (int j2 = ntiles; j2 < L_ / 64; j2++) {
#pragma unroll
            for (int c = 0; c < 8; c++) {
                int id = c * 256 + tid;
                int r = id >> 4, c4 = (id & 15) << 2;
                *(float4*)&attn[(size_t)(q0 + r) * L_ + j2 * 64 + c4] = z4;
            }
        }
    }

    // ---------------- pass A: row sums only ----------------
    float l0 = 0.f, l1 = 0.f;
    for (int jt = 0; jt < ntiles; jt++) {
        cp_wait0();
        __syncthreads();
        if (jt + 1 < ntiles) issueK(jt + 1);

        const uint32_t kh_b = sb + (jt & 1) * 36864;
        const uint32_t kl_b = kh_b + 9216;

#pragma unroll
        for (int np = 0; np < 4; np++) {
            float sc[2][4] = {};
            const uint32_t rowb = (uint32_t)(16 * np * 36 * 4) + kvoff;
#pragma unroll
            for (int kc = 0; kc < 4; kc++) {
                uint32_t kh4[4], kl4[4];
                ldm4(kh4, kh_b + rowb + kc * 32);
                ldm4(kl4, kl_b + rowb + kc * 32);
                mma_bf16(sc[0], qh[kc], kh4);
                mma_bf16(sc[0], qh[kc], kl4);
                mma_bf16(sc[0], ql[kc], kh4);
                mma_bf16(sc[1], qh[kc], kh4 + 2);
                mma_bf16(sc[1], qh[kc], kl4 + 2);
                mma_bf16(sc[1], ql[kc], kh4 + 2);
            }
#pragma unroll
            for (int u = 0; u < 2; u++) {
                const int nt = 2 * np + u;
                int jc = jt * 64 + nt * 8 + 2 * tig;
                float p0 = __expf(sc[u][0] * scale); if (jc     > grow0) p0 = 0.f;
                float p1 = __expf(sc[u][1] * scale); if (jc + 1 > grow0) p1 = 0.f;
                float p2 = __expf(sc[u][2] * scale); if (jc     > grow1) p2 = 0.f;
                float p3 = __expf(sc[u][3] * scale); if (jc + 1 > grow1) p3 = 0.f;
                l0 += p0 + p1;
                l1 += p2 + p3;
            }
        }
    }
    // reduce over quad; each thread owns inv for its 2 rows
    l0 += __shfl_xor_sync(0xffffffffu, l0, 1);
    l0 += __shfl_xor_sync(0xffffffffu, l0, 2);
    l1 += __shfl_xor_sync(0xffffffffu, l1, 1);
    l1 += __shfl_xor_sync(0xffffffffu, l1, 2);
    const float inv0 = 1.f / l0, inv1 = 1.f / l1;

    // ---------------- pass B: normalized P + PV ----------------
    issue(0);
    float oa[8][4] = {};

    for (int jt = 0; jt < ntiles; jt++) {
        cp_wait0();
        __syncthreads();
        if (jt + 1 < ntiles) issue(jt + 1);

        const uint32_t kh_b = sb + (jt & 1) * 36864;
        const uint32_t kl_b = kh_b + 9216;
        const uint32_t vh_b = kh_b + 18432;
        const uint32_t vl_b = kh_b + 27648;

#pragma unroll
        for (int np = 0; np < 4; np++) {
            float sc[2][4] = {};
            const uint32_t rowb = (uint32_t)(16 * np * 36 * 4) + kvoff;
#pragma unroll
            for (int kc = 0; kc < 4; kc++) {
                uint32_t kh4[4], kl4[4];
                ldm4(kh4, kh_b + rowb + kc * 32);
                ldm4(kl4, kl_b + rowb + kc * 32);
                mma_bf16(sc[0], qh[kc], kh4);
                mma_bf16(sc[0], qh[kc], kl4);
                mma_bf16(sc[0], ql[kc], kh4);
                mma_bf16(sc[1], qh[kc], kh4 + 2);
                mma_bf16(sc[1], qh[kc], kl4 + 2);
                mma_bf16(sc[1], ql[kc], kh4 + 2);
            }
#pragma unroll
            for (int u = 0; u < 2; u++) {
                const int nt = 2 * np + u;
                int jc = jt * 64 + nt * 8 + 2 * tig;
                float p0 = __expf(sc[u][0] * scale); if (jc     > grow0) p0 = 0.f;
                float p1 = __expf(sc[u][1] * scale); if (jc + 1 > grow0) p1 = 0.f;
                float p2 = __expf(sc[u][2] * scale); if (jc     > grow1) p2 = 0.f;
                float p3 = __expf(sc[u][3] * scale); if (jc + 1 > grow1) p3 = 0.f;
                p0 *= inv0; p1 *= inv0; p2 *= inv1; p3 *= inv1;   // normalize now
                uint32_t h, l;
                split_pack(p0, p1, h, l);
                P2h[(wm + gr) * 36 + nt * 4 + tig] = h;
                P2l[(wm + gr) * 36 + nt * 4 + tig] = l;
                split_pack(p2, p3, h, l);
                P2h[(wm + gr + 8) * 36 + nt * 4 + tig] = h;
                P2l[(wm + gr + 8) * 36 + nt * 4 + tig] = l;
                *(float2*)&attn[(size_t)grow0 * L_ + jc] = make_float2(p0, p1);
                *(float2*)&attn[(size_t)grow1 * L_ + jc] = make_float2(p2, p3);
            }
        }
        __syncwarp();   // P2 rows are warp-private

        // O += P_norm V
#pragma unroll
        for (int kc = 0; kc < 4; kc++) {
            uint32_t ph[4], plo[4];
            ldm4(ph,  p2h_b + poff + kc * 32);
            ldm4(plo, p2l_b + poff + kc * 32);
#pragma unroll
            for (int np = 0; np < 4; np++) {
                const uint32_t rowb = (uint32_t)(16 * np * 36 * 4) + kvoff;
                uint32_t vh4[4], vl4[4];
                ldm4(vh4, vh_b + rowb + kc * 32);
                ldm4(vl4, vl_b + rowb + kc * 32);
                mma_bf16(oa[2 * np], ph, vh4);
                mma_bf16(oa[2 * np], ph, vl4);
                mma_bf16(oa[2 * np], plo, vh4);
                mma_bf16(oa[2 * np + 1], ph, vh4 + 2);
                mma_bf16(oa[2 * np + 1], ph, vl4 + 2);
                mma_bf16(oa[2 * np + 1], plo, vh4 + 2);
            }
        }
    }

    // O (already normalized) -> packed global (feeds outproj cp.async)
#pragma unroll
    for (int nt = 0; nt < 8; nt++) {
        uint32_t h, l;
        split_pack(oa[nt][0], oa[nt][1], h, l);
        size_t ia = ((size_t)bh * L_ + grow0) * 32 + nt * 4 + tig;
        g_Ohh[ia] = h; g_Ohl[ia] = l;
        split_pack(oa[nt][2], oa[nt][3], h, l);
        size_t ib = ((size_t)bh * L_ + grow1) * 32 + nt * 4 + tig;
        g_Ohh[ib] = h; g_Ohl[ib] = l;
    }
}

constexpr int ATTN_SMEM = (27648 + 128) * 4;   // 111104 B

// ---------------------------------------------------------------------------
extern "C" void kernel_launch(void* const* d_in, const int* in_sizes, int n_in,
                              void* d_out, int out_size)
{
    const float* qkv[3] = {nullptr, nullptr, nullptr};
    const float* Ws[4]  = {nullptr, nullptr, nullptr, nullptr};
    int nqkv = 0, nw = 0;
    for (int i = 0; i < n_in; i++) {
        if (in_sizes[i] == NTOK * E_) { if (nqkv < 3) qkv[nqkv++] = (const float*)d_in[i]; }
        else if (in_sizes[i] == E_ * E_) { if (nw < 4) Ws[nw++] = (const float*)d_in[i]; }
    }
    float* out  = (float*)d_out;
    float* attn = out + (size_t)B_ * L_ * E_;

    cudaFuncSetAttribute(proj_tc, cudaFuncAttributeMaxDynamicSharedMemorySize, GEMM_SMEM);
    cudaFuncSetAttribute(outproj_tc, cudaFuncAttributeMaxDynamicSharedMemorySize, GEMM_SMEM);
    cudaFuncSetAttribute(attn_tc, cudaFuncAttributeMaxDynamicSharedMemorySize, ATTN_SMEM);

    pack_combo<<<(IN8 + W8 + 255) / 256, 256>>>(
        (const float4*)qkv[0], (const float4*)Ws[0], nullptr, 0);
    pack_combo<<<(IN8 + W8 + 255) / 256, 256>>>(
        (const float4*)qkv[1], (const float4*)Ws[1], nullptr, 1);
    pack_combo<<<(IN8 + 2 * W8 + 255) / 256, 256>>>(
        (const float4*)qkv[2], (const float4*)Ws[2], (const float4*)Ws[3], 2);

    proj_tc<<<dim3(E_ / 128, NTOK / 128, 3), 256, GEMM_SMEM>>>();
    attn_tc<<<dim3(L_ / 128, BH), 256, ATTN_SMEM>>>(attn);
    outproj_tc<<<dim3(E_ / 128, NTOK / 128), 256, GEMM_SMEM>>>(out);
}